// round 10
// baseline (speedup 1.0000x reference)
#include <cuda_runtime.h>
#include <cuda_fp16.h>
#include <math.h>
#include <stdint.h>

#define NQ    20
#define DIM   (1u << NQ)
#define BATCH 4
#define LOWC  4
#define SMAP(i) ((i) + ((i) >> 3))   // smem pad map: +1 float2 per 8 (conflict relief)

// ---------------- global scratch ----------------
static __device__ float2 g_psi[(size_t)BATCH * DIM];   // state after pass_high
// 7 packed-fp16 planes [plane][b][kpair][col], uint32 = {k even (lo), k odd (hi)}
// planes: 0=rH 1=rL 2=iH 3=iL 4=dH 5=dL 6=sH   (d = i - r, s = r + i)
static __device__ uint32_t g_tp32[(size_t)7 * BATCH * (DIM / 2)];
static __device__ float2 g_fused[NQ - 1][16];          // fused 4x4 gates
#define PSTR ((size_t)BATCH << 19)                     // uint32s per plane

// ---------------- complex helpers ----------------
__device__ __forceinline__ float2 cmul(float2 a, float2 b) {
    return make_float2(a.x * b.x - a.y * b.y, a.x * b.y + a.y * b.x);
}
__device__ __forceinline__ float2 cadd(float2 a, float2 b) {
    return make_float2(a.x + b.x, a.y + b.y);
}
__device__ void mat2mul(const float2* A, const float2* B, float2* C) {
    for (int i = 0; i < 2; i++)
        for (int j = 0; j < 2; j++) {
            float2 s = make_float2(0.f, 0.f);
            for (int k = 0; k < 2; k++) s = cadd(s, cmul(A[i * 2 + k], B[k * 2 + j]));
            C[i * 2 + j] = s;
        }
}
__device__ void mat4mul(const float2* A, const float2* B, float2* C) {
    for (int i = 0; i < 4; i++)
        for (int j = 0; j < 4; j++) {
            float2 s = make_float2(0.f, 0.f);
            for (int k = 0; k < 4; k++) s = cadd(s, cmul(A[i * 4 + k], B[k * 4 + j]));
            C[i * 4 + j] = s;
        }
}
__device__ void kron22(const float2* A, const float2* B, float2* C) {
    for (int i2 = 0; i2 < 2; i2++)
        for (int i1 = 0; i1 < 2; i1++)
            for (int j2 = 0; j2 < 2; j2++)
                for (int j1 = 0; j1 < 2; j1++)
                    C[(i2 * 2 + i1) * 4 + (j2 * 2 + j1)] = cmul(A[i2 * 2 + j2], B[i1 * 2 + j1]);
}

// ---------------- gate precompute ----------------
__global__ void precompute_gates(const float* __restrict__ w) {
    const float WM = 0.6324555320336759f;  // sqrt(2/5)
    __shared__ float2 U1[NQ][4];
    __shared__ float2 U2[NQ][4];
    int t = threadIdx.x;
    if (t < NQ) {
        for (int layer = 0; layer < 2; layer++) {
            int base = (layer == 0) ? 0 : (6 * NQ - 3);
            float tx = w[base + 3 * t]     * WM;
            float ty = w[base + 3 * t + 1] * WM;
            float tz = w[base + 3 * t + 2] * WM;
            float cx = cosf(0.5f * tx), sx = sinf(0.5f * tx);
            float cy = cosf(0.5f * ty), sy = sinf(0.5f * ty);
            float cz = cosf(0.5f * tz), sz = sinf(0.5f * tz);
            float2 Rx[4] = { {cx,0.f}, {0.f,-sx}, {0.f,-sx}, {cx,0.f} };
            float2 Ry[4] = { {cy,0.f}, {-sy,0.f}, {sy,0.f},  {cy,0.f} };
            float2 Rz[4] = { {cz,-sz}, {0.f,0.f}, {0.f,0.f}, {cz,sz} };
            float2 T[4], U[4];
            mat2mul(Ry, Rx, T);
            mat2mul(Rz, T, U);
            float2* dst = (layer == 0) ? U1[t] : U2[t];
            for (int i = 0; i < 4; i++) dst[i] = U[i];
        }
    }
    __syncthreads();
    if (t < NQ - 1) {
        float a = w[3 * NQ + 3 * t]     * WM;
        float b = w[3 * NQ + 3 * t + 1] * WM;
        float c = w[3 * NQ + 3 * t + 2] * WM;
        float ca = cosf(0.5f * a), sa = sinf(0.5f * a);
        float cb = cosf(0.5f * b), sb = sinf(0.5f * b);
        float cc = cosf(0.5f * c), sc = sinf(0.5f * c);
        float2 Rxx[16], Ryy[16], Rzz[16];
        for (int i = 0; i < 16; i++) {
            Rxx[i] = make_float2(0.f, 0.f);
            Ryy[i] = make_float2(0.f, 0.f);
            Rzz[i] = make_float2(0.f, 0.f);
        }
        for (int i = 0; i < 4; i++) {
            Rxx[i * 4 + i] = make_float2(ca, 0.f);
            Ryy[i * 4 + i] = make_float2(cb, 0.f);
        }
        Rxx[3]  = make_float2(0.f, -sa);
        Rxx[6]  = make_float2(0.f, -sa);
        Rxx[9]  = make_float2(0.f, -sa);
        Rxx[12] = make_float2(0.f, -sa);
        Ryy[3]  = make_float2(0.f,  sb);
        Ryy[6]  = make_float2(0.f, -sb);
        Ryy[9]  = make_float2(0.f, -sb);
        Ryy[12] = make_float2(0.f,  sb);
        Rzz[0]  = make_float2(cc, -sc);
        Rzz[5]  = make_float2(cc,  sc);
        Rzz[10] = make_float2(cc,  sc);
        Rzz[15] = make_float2(cc, -sc);
        float2 T[16], Bq[16];
        mat4mul(Ryy, Rxx, T);
        mat4mul(Rzz, T, Bq);

        float2 I2m[4] = { {1.f,0.f},{0.f,0.f},{0.f,0.f},{1.f,0.f} };
        float2 R[16], G[16];
        if (t == 0) kron22(U1[0], U1[1], R);
        else        kron22(I2m, U1[t + 1], R);
        mat4mul(Bq, R, G);
        if (t >= 10) {
            float2 L[16], G2[16];
            if (t == 18) kron22(U2[18], U2[19], L);
            else         kron22(U2[t], I2m, L);
            mat4mul(L, G, G2);
            for (int i = 0; i < 16; i++) G[i] = G2[i];
        }
        for (int i = 0; i < 16; i++) g_fused[t][i] = G[i];
    }
}

// ---------------- 4-dim gate on registers ----------------
__device__ __forceinline__ void gate4(float2* v, const float2* m) {
    float2 a = v[0], b = v[1], c = v[2], d = v[3];
#pragma unroll
    for (int j = 0; j < 4; j++) {
        float2 r = cmul(m[4 * j], a);
        r = cadd(r, cmul(m[4 * j + 1], b));
        r = cadd(r, cmul(m[4 * j + 2], c));
        r = cadd(r, cmul(m[4 * j + 3], d));
        v[j] = r;
    }
}

// ---------------- 2q gate on padded shared tile ----------------
__device__ __forceinline__ void apply2q(float2* s, int nquads, int pl,
                                        const float2* __restrict__ Mg,
                                        int tid, int nth) {
    float2 m[16];
#pragma unroll
    for (int i = 0; i < 16; i++) m[i] = Mg[i];
    for (int p = tid; p < nquads; p += nth) {
        int lowm = p & ((1 << pl) - 1);
        int i0 = ((p >> pl) << (pl + 2)) | lowm;
        int j0 = SMAP(i0);
        int j1 = SMAP(i0 | (1 << pl));
        int j2 = SMAP(i0 | (2 << pl));
        int j3 = SMAP(i0 | (3 << pl));
        float2 v[4] = { s[j0], s[j1], s[j2], s[j3] };
        gate4(v, m);
        s[j0] = v[0];
        s[j1] = v[1];
        s[j2] = v[2];
        s[j3] = v[3];
    }
}

// ---------------- Pass H: bonds 0..8 on combined bits 11..2 ----------------
__global__ void pass_high(const float* __restrict__ x) {
    __shared__ float2 s[4608];       // SMAP(4095)=4606
    const int b    = blockIdx.y;
    const int low0 = blockIdx.x * LOWC;
    const int tid  = threadIdx.x;
    const float* xb = x + (size_t)b * DIM;

    for (int e = tid; e < 4096; e += 256) {
        int l = e & (LOWC - 1), h = e >> 2;
        s[SMAP(e)] = make_float2(xb[h * 1024 + low0 + l], 0.f);
    }
    __syncthreads();
    for (int q = 0; q < 9; q++) {
        apply2q(s, 1024, (8 - q) + 2, g_fused[q], tid, 256);
        __syncthreads();
    }
    float2* pb = g_psi + (size_t)b * DIM;
    for (int e = tid; e < 4096; e += 256) {
        int l = e & (LOWC - 1), h = e >> 2;
        pb[h * 1024 + low0 + l] = s[SMAP(e)];
    }
}

// ---------------- fp16 pack helpers ----------------
__device__ __forceinline__ uint32_t pk2(float a, float b) {
    __half ha = __float2half_rn(a), hb = __float2half_rn(b);
    return (uint32_t)__half_as_ushort(ha) | ((uint32_t)__half_as_ushort(hb) << 16);
}

// ---------------- Pass L: smem bonds 9..16, in-reg bonds 17,18 + pack ----------------
__global__ void pass_low() {
    __shared__ float2 s[2304];       // SMAP(2047)=2302
    const int b = blockIdx.y;
    const size_t base = (size_t)b * DIM + (size_t)blockIdx.x * 2048;
    const int tid = threadIdx.x;

    for (int e = tid; e < 2048; e += 256) s[SMAP(e)] = g_psi[base + e];
    __syncthreads();
    for (int q = 9; q < 17; q++) {              // pl = 18-q : 9..2
        apply2q(s, 512, 18 - q, g_fused[q], tid, 256);
        __syncthreads();
    }

    // bonds 17 (bits 2,1) and 18 (bits 1,0) in registers over 8-column octets,
    // fused with the 7-plane fp16 pack.
    if (tid < 128) {
        float2 ve[8], vo[8];
        const int sb = 9 * tid;                 // SMAP(8*tid)
#pragma unroll
        for (int j = 0; j < 8; j++) ve[j] = s[sb + j];           // k even
#pragma unroll
        for (int j = 0; j < 8; j++) vo[j] = s[1152 + sb + j];    // k odd: SMAP(1024+8t+j)
        {
            float2 m[16];
#pragma unroll
            for (int i = 0; i < 16; i++) m[i] = g_fused[17][i];
            float2 t4[4];
            t4[0] = ve[0]; t4[1] = ve[2]; t4[2] = ve[4]; t4[3] = ve[6];
            gate4(t4, m);
            ve[0] = t4[0]; ve[2] = t4[1]; ve[4] = t4[2]; ve[6] = t4[3];
            t4[0] = ve[1]; t4[1] = ve[3]; t4[2] = ve[5]; t4[3] = ve[7];
            gate4(t4, m);
            ve[1] = t4[0]; ve[3] = t4[1]; ve[5] = t4[2]; ve[7] = t4[3];
            t4[0] = vo[0]; t4[1] = vo[2]; t4[2] = vo[4]; t4[3] = vo[6];
            gate4(t4, m);
            vo[0] = t4[0]; vo[2] = t4[1]; vo[4] = t4[2]; vo[6] = t4[3];
            t4[0] = vo[1]; t4[1] = vo[3]; t4[2] = vo[5]; t4[3] = vo[7];
            gate4(t4, m);
            vo[1] = t4[0]; vo[3] = t4[1]; vo[5] = t4[2]; vo[7] = t4[3];
        }
        {
            float2 m[16];
#pragma unroll
            for (int i = 0; i < 16; i++) m[i] = g_fused[18][i];
            gate4(ve, m);
            gate4(ve + 4, m);
            gate4(vo, m);
            gate4(vo + 4, m);
        }

        const size_t ci = ((size_t)b << 19) + ((size_t)blockIdx.x << 10) + 8 * (size_t)tid;
        uint32_t w[8];
        // plane 0: rH
#pragma unroll
        for (int j = 0; j < 8; j++) {
            __half he = __float2half_rn(ve[j].x), ho = __float2half_rn(vo[j].x);
            w[j] = (uint32_t)__half_as_ushort(he) | ((uint32_t)__half_as_ushort(ho) << 16);
        }
        *(uint4*)(g_tp32 + 0 * PSTR + ci) = *(uint4*)w;
        *(uint4*)(g_tp32 + 0 * PSTR + ci + 4) = *(uint4*)(w + 4);
        // plane 1: rL
#pragma unroll
        for (int j = 0; j < 8; j++) {
            __half he = __float2half_rn(ve[j].x), ho = __float2half_rn(vo[j].x);
            w[j] = pk2(ve[j].x - __half2float(he), vo[j].x - __half2float(ho));
        }
        *(uint4*)(g_tp32 + 1 * PSTR + ci) = *(uint4*)w;
        *(uint4*)(g_tp32 + 1 * PSTR + ci + 4) = *(uint4*)(w + 4);
        // plane 2: iH
#pragma unroll
        for (int j = 0; j < 8; j++) {
            __half he = __float2half_rn(ve[j].y), ho = __float2half_rn(vo[j].y);
            w[j] = (uint32_t)__half_as_ushort(he) | ((uint32_t)__half_as_ushort(ho) << 16);
        }
        *(uint4*)(g_tp32 + 2 * PSTR + ci) = *(uint4*)w;
        *(uint4*)(g_tp32 + 2 * PSTR + ci + 4) = *(uint4*)(w + 4);
        // plane 3: iL
#pragma unroll
        for (int j = 0; j < 8; j++) {
            __half he = __float2half_rn(ve[j].y), ho = __float2half_rn(vo[j].y);
            w[j] = pk2(ve[j].y - __half2float(he), vo[j].y - __half2float(ho));
        }
        *(uint4*)(g_tp32 + 3 * PSTR + ci) = *(uint4*)w;
        *(uint4*)(g_tp32 + 3 * PSTR + ci + 4) = *(uint4*)(w + 4);
        // plane 4: dH  (d = i - r)
#pragma unroll
        for (int j = 0; j < 8; j++) {
            __half he = __float2half_rn(ve[j].y - ve[j].x), ho = __float2half_rn(vo[j].y - vo[j].x);
            w[j] = (uint32_t)__half_as_ushort(he) | ((uint32_t)__half_as_ushort(ho) << 16);
        }
        *(uint4*)(g_tp32 + 4 * PSTR + ci) = *(uint4*)w;
        *(uint4*)(g_tp32 + 4 * PSTR + ci + 4) = *(uint4*)(w + 4);
        // plane 5: dL
#pragma unroll
        for (int j = 0; j < 8; j++) {
            float de = ve[j].y - ve[j].x, dd = vo[j].y - vo[j].x;
            __half he = __float2half_rn(de), ho = __float2half_rn(dd);
            w[j] = pk2(de - __half2float(he), dd - __half2float(ho));
        }
        *(uint4*)(g_tp32 + 5 * PSTR + ci) = *(uint4*)w;
        *(uint4*)(g_tp32 + 5 * PSTR + ci + 4) = *(uint4*)(w + 4);
        // plane 6: sH  (s = r + i)
#pragma unroll
        for (int j = 0; j < 8; j++)
            w[j] = pk2(ve[j].x + ve[j].y, vo[j].x + vo[j].y);
        *(uint4*)(g_tp32 + 6 * PSTR + ci) = *(uint4*)w;
        *(uint4*)(g_tp32 + 6 * PSTR + ci + 4) = *(uint4*)(w + 4);
    }
}

// ---------------- rdm GEMM v7: k32 stages, double buffer, fp16 Gauss ----------------
#define AS 72            // A smem col stride (uint32), ≡8 mod 32 -> conflict-free
#define BS 136           // B stride
#define A_PL_B (16 * AS * 4)           // 4608 B per A plane (16 kpairs = k32)
#define B_PL_B (16 * BS * 4)           // 8704 B per B plane
#define A_ALL_B (6 * A_PL_B)           // 27648
#define STG_B  (A_ALL_B + 3 * B_PL_B)  // 53760
#define NSTG   2
#define GEMM_SMEM (NSTG * STG_B)       // 107520

__device__ __forceinline__ void mma_f16(float* d, uint32_t a0, uint32_t a1,
                                        uint32_t a2, uint32_t a3,
                                        uint32_t b0, uint32_t b1) {
    asm volatile(
        "mma.sync.aligned.m16n8k16.row.col.f32.f16.f16.f32 "
        "{%0,%1,%2,%3},{%4,%5,%6,%7},{%8,%9},{%0,%1,%2,%3};"
        : "+f"(d[0]), "+f"(d[1]), "+f"(d[2]), "+f"(d[3])
        : "r"(a0), "r"(a1), "r"(a2), "r"(a3), "r"(b0), "r"(b1));
}
__device__ __forceinline__ void cp_async16(void* smem_ptr, const void* gptr) {
    uint32_t sa = (uint32_t)__cvta_generic_to_shared(smem_ptr);
    asm volatile("cp.async.cg.shared.global [%0], [%1], 16;" :: "r"(sa), "l"(gptr));
}
__device__ __forceinline__ void cp_commit() { asm volatile("cp.async.commit_group;"); }
__device__ __forceinline__ void cp_wait1()  { asm volatile("cp.async.wait_group 1;"); }

__global__ void __launch_bounds__(256, 2) rdm_gemm(float* __restrict__ out) {
    extern __shared__ char smem[];

    int tcc = 0, rem = blockIdx.x;
    while (rem >= 2 * tcc + 2) { rem -= 2 * tcc + 2; tcc++; }
    int ta = rem;

    const int b = blockIdx.y;
    const int a0b = ta * 64, c0b = tcc * 128;
    const int tid  = threadIdx.x;
    const int wid  = tid >> 5;
    const int lane = tid & 31;
    const int g    = lane >> 2;
    const int t4   = lane & 3;
    const int warpM = wid & 1;
    const int warpN = wid >> 1;

    float acc[3][2][4][4] = {};

    auto stage = [&](int st) {
        char* sb = smem + (st & 1) * STG_B;
        const int kr0 = st * 16;
#pragma unroll
        for (int j = 0; j < 12; j++) {
            int cid = tid + j * 256;
            if (cid < 1536) {
                int pl = cid >> 8;
                int rm = cid & 255;
                int kp = rm >> 4, ch = rm & 15;
                const uint32_t* src = g_tp32 + (size_t)pl * PSTR + ((size_t)b << 19)
                                    + ((size_t)(kr0 + kp) << 10) + a0b + ch * 4;
                cp_async16(sb + pl * A_PL_B + kp * (AS * 4) + ch * 16, src);
            } else {
                int d2 = cid - 1536;
                int p = d2 >> 9;
                int rm = d2 & 511;
                int kp = rm >> 5, ch = rm & 31;
                int gp = (p == 0) ? 0 : ((p == 1) ? 2 : 6);
                const uint32_t* src = g_tp32 + (size_t)gp * PSTR + ((size_t)b << 19)
                                    + ((size_t)(kr0 + kp) << 10) + c0b + ch * 4;
                cp_async16(sb + A_ALL_B + p * B_PL_B + kp * (BS * 4) + ch * 16, src);
            }
        }
        cp_commit();
    };

    stage(0);
    stage(1);

    for (int st = 0; st < 32; st++) {
        cp_wait1();
        __syncthreads();
        const char* sb = smem + (st & 1) * STG_B;

#pragma unroll
        for (int half = 0; half < 2; half++) {
            const int kofs = half * 8;
#pragma unroll
            for (int p = 0; p < 3; p++) {
                const uint32_t* paH = (const uint32_t*)(sb + (2 * p) * A_PL_B) + kofs * AS;
                const uint32_t* paL = (const uint32_t*)(sb + (2 * p + 1) * A_PL_B) + kofs * AS;
                const uint32_t* pB  = (const uint32_t*)(sb + A_ALL_B + p * B_PL_B) + kofs * BS;

                uint32_t Ah[2][4], Al[2][4];
#pragma unroll
                for (int mi = 0; mi < 2; mi++) {
                    int col = warpM * 32 + mi * 16 + g;
                    Ah[mi][0] = paH[t4 * AS + col];
                    Ah[mi][1] = paH[t4 * AS + col + 8];
                    Ah[mi][2] = paH[(t4 + 4) * AS + col];
                    Ah[mi][3] = paH[(t4 + 4) * AS + col + 8];
                    Al[mi][0] = paL[t4 * AS + col];
                    Al[mi][1] = paL[t4 * AS + col + 8];
                    Al[mi][2] = paL[(t4 + 4) * AS + col];
                    Al[mi][3] = paL[(t4 + 4) * AS + col + 8];
                }
                uint32_t Bf[4][2];
#pragma unroll
                for (int ni = 0; ni < 4; ni++) {
                    int col = warpN * 32 + ni * 8 + g;
                    Bf[ni][0] = pB[t4 * BS + col];
                    Bf[ni][1] = pB[(t4 + 4) * BS + col];
                }
#pragma unroll
                for (int ni = 0; ni < 4; ni++)
#pragma unroll
                    for (int mi = 0; mi < 2; mi++)
                        mma_f16(acc[p][mi][ni], Ah[mi][0], Ah[mi][1], Ah[mi][2], Ah[mi][3],
                                Bf[ni][0], Bf[ni][1]);
#pragma unroll
                for (int ni = 0; ni < 4; ni++)
#pragma unroll
                    for (int mi = 0; mi < 2; mi++)
                        mma_f16(acc[p][mi][ni], Al[mi][0], Al[mi][1], Al[mi][2], Al[mi][3],
                                Bf[ni][0], Bf[ni][1]);
            }
        }
        __syncthreads();

        if (st + 2 < 32) stage(st + 2);
        else             cp_commit();
    }

    float2* out2 = (float2*)out;
#pragma unroll
    for (int mi = 0; mi < 2; mi++)
#pragma unroll
        for (int ni = 0; ni < 4; ni++)
#pragma unroll
            for (int r = 0; r < 4; r++) {
                int a = a0b + warpM * 32 + mi * 16 + g + ((r & 2) ? 8 : 0);
                int c = c0b + warpN * 32 + ni * 8 + 2 * t4 + (r & 1);
                float t1 = acc[0][mi][ni][r];
                float t2 = acc[1][mi][ni][r];
                float t3 = acc[2][mi][ni][r];
                float vr = t1 + t2;
                float vi = t3 + t1 - t2;
                if (a <= c)
                    out2[(size_t)(b * 1024 + a) * 1024 + c] = make_float2(vr, vi);
                if (a < c)
                    out2[(size_t)(b * 1024 + c) * 1024 + a] = make_float2(vr, -vi);
            }
}

// ---------------- launch ----------------
extern "C" void kernel_launch(void* const* d_in, const int* in_sizes, int n_in,
                              void* d_out, int out_size) {
    const float* x = (const float*)d_in[0];
    const float* w = (const float*)d_in[1];
    float* out = (float*)d_out;

    cudaFuncSetAttribute(rdm_gemm, cudaFuncAttributeMaxDynamicSharedMemorySize, GEMM_SMEM);

    precompute_gates<<<1, 32>>>(w);
    pass_high<<<dim3(1024 / LOWC, BATCH), 256>>>(x);
    pass_low<<<dim3(512, BATCH), 256>>>();
    rdm_gemm<<<dim3(72, BATCH), 256, GEMM_SMEM>>>(out);
}

// round 11
// speedup vs baseline: 1.2249x; 1.2249x over previous
#include <cuda_runtime.h>
#include <cuda_fp16.h>
#include <math.h>
#include <stdint.h>

#define NQ    20
#define DIM   (1u << NQ)
#define BATCH 4
#define LOWC  4

// ---------------- global scratch ----------------
static __device__ float2 g_psi[(size_t)BATCH * DIM];   // state after pass_high
// 6 packed-fp16 planes [plane][b][kpair][col], uint32 = {k even (lo), k odd (hi)}
// planes: 0=rH 1=rL 2=iH 3=iL 4=dH 5=sH   (d = i - r, s = r + i)
static __device__ uint32_t g_tp32[(size_t)6 * BATCH * (DIM / 2)];
static __device__ float2 g_fused[NQ - 1][16];          // fused 4x4 gates
#define PSTR ((size_t)BATCH << 19)                     // uint32s per plane

// ---------------- complex helpers ----------------
__device__ __forceinline__ float2 cmul(float2 a, float2 b) {
    return make_float2(a.x * b.x - a.y * b.y, a.x * b.y + a.y * b.x);
}
__device__ __forceinline__ float2 cadd(float2 a, float2 b) {
    return make_float2(a.x + b.x, a.y + b.y);
}
__device__ void mat2mul(const float2* A, const float2* B, float2* C) {
    for (int i = 0; i < 2; i++)
        for (int j = 0; j < 2; j++) {
            float2 s = make_float2(0.f, 0.f);
            for (int k = 0; k < 2; k++) s = cadd(s, cmul(A[i * 2 + k], B[k * 2 + j]));
            C[i * 2 + j] = s;
        }
}
__device__ void mat4mul(const float2* A, const float2* B, float2* C) {
    for (int i = 0; i < 4; i++)
        for (int j = 0; j < 4; j++) {
            float2 s = make_float2(0.f, 0.f);
            for (int k = 0; k < 4; k++) s = cadd(s, cmul(A[i * 4 + k], B[k * 4 + j]));
            C[i * 4 + j] = s;
        }
}
__device__ void kron22(const float2* A, const float2* B, float2* C) {
    for (int i2 = 0; i2 < 2; i2++)
        for (int i1 = 0; i1 < 2; i1++)
            for (int j2 = 0; j2 < 2; j2++)
                for (int j1 = 0; j1 < 2; j1++)
                    C[(i2 * 2 + i1) * 4 + (j2 * 2 + j1)] = cmul(A[i2 * 2 + j2], B[i1 * 2 + j1]);
}

// ---------------- gate precompute ----------------
__global__ void precompute_gates(const float* __restrict__ w) {
    const float WM = 0.6324555320336759f;  // sqrt(2/5)
    __shared__ float2 U1[NQ][4];
    __shared__ float2 U2[NQ][4];
    int t = threadIdx.x;
    if (t < NQ) {
        for (int layer = 0; layer < 2; layer++) {
            int base = (layer == 0) ? 0 : (6 * NQ - 3);
            float tx = w[base + 3 * t]     * WM;
            float ty = w[base + 3 * t + 1] * WM;
            float tz = w[base + 3 * t + 2] * WM;
            float cx = cosf(0.5f * tx), sx = sinf(0.5f * tx);
            float cy = cosf(0.5f * ty), sy = sinf(0.5f * ty);
            float cz = cosf(0.5f * tz), sz = sinf(0.5f * tz);
            float2 Rx[4] = { {cx,0.f}, {0.f,-sx}, {0.f,-sx}, {cx,0.f} };
            float2 Ry[4] = { {cy,0.f}, {-sy,0.f}, {sy,0.f},  {cy,0.f} };
            float2 Rz[4] = { {cz,-sz}, {0.f,0.f}, {0.f,0.f}, {cz,sz} };
            float2 T[4], U[4];
            mat2mul(Ry, Rx, T);
            mat2mul(Rz, T, U);
            float2* dst = (layer == 0) ? U1[t] : U2[t];
            for (int i = 0; i < 4; i++) dst[i] = U[i];
        }
    }
    __syncthreads();
    if (t < NQ - 1) {
        float a = w[3 * NQ + 3 * t]     * WM;
        float b = w[3 * NQ + 3 * t + 1] * WM;
        float c = w[3 * NQ + 3 * t + 2] * WM;
        float ca = cosf(0.5f * a), sa = sinf(0.5f * a);
        float cb = cosf(0.5f * b), sb = sinf(0.5f * b);
        float cc = cosf(0.5f * c), sc = sinf(0.5f * c);
        float2 Rxx[16], Ryy[16], Rzz[16];
        for (int i = 0; i < 16; i++) {
            Rxx[i] = make_float2(0.f, 0.f);
            Ryy[i] = make_float2(0.f, 0.f);
            Rzz[i] = make_float2(0.f, 0.f);
        }
        for (int i = 0; i < 4; i++) {
            Rxx[i * 4 + i] = make_float2(ca, 0.f);
            Ryy[i * 4 + i] = make_float2(cb, 0.f);
        }
        Rxx[3]  = make_float2(0.f, -sa);
        Rxx[6]  = make_float2(0.f, -sa);
        Rxx[9]  = make_float2(0.f, -sa);
        Rxx[12] = make_float2(0.f, -sa);
        Ryy[3]  = make_float2(0.f,  sb);
        Ryy[6]  = make_float2(0.f, -sb);
        Ryy[9]  = make_float2(0.f, -sb);
        Ryy[12] = make_float2(0.f,  sb);
        Rzz[0]  = make_float2(cc, -sc);
        Rzz[5]  = make_float2(cc,  sc);
        Rzz[10] = make_float2(cc,  sc);
        Rzz[15] = make_float2(cc, -sc);
        float2 T[16], Bq[16];
        mat4mul(Ryy, Rxx, T);
        mat4mul(Rzz, T, Bq);

        float2 I2m[4] = { {1.f,0.f},{0.f,0.f},{0.f,0.f},{1.f,0.f} };
        float2 R[16], G[16];
        if (t == 0) kron22(U1[0], U1[1], R);
        else        kron22(I2m, U1[t + 1], R);
        mat4mul(Bq, R, G);
        if (t >= 10) {
            float2 L[16], G2[16];
            if (t == 18) kron22(U2[18], U2[19], L);
            else         kron22(U2[t], I2m, L);
            mat4mul(L, G, G2);
            for (int i = 0; i < 16; i++) G[i] = G2[i];
        }
        for (int i = 0; i < 16; i++) g_fused[t][i] = G[i];
    }
}

// ---------------- 2q gate on shared tile (lean, proven) ----------------
__device__ __forceinline__ void apply2q(float2* s, int nquads, int pl,
                                        const float2* __restrict__ Mg,
                                        int tid, int nth) {
    float2 m[16];
#pragma unroll
    for (int i = 0; i < 16; i++) m[i] = Mg[i];
    for (int p = tid; p < nquads; p += nth) {
        int lowm = p & ((1 << pl) - 1);
        int i0 = ((p >> pl) << (pl + 2)) | lowm;
        float2 v0 = s[i0];
        float2 v1 = s[i0 | (1 << pl)];
        float2 v2 = s[i0 | (2 << pl)];
        float2 v3 = s[i0 | (3 << pl)];
#pragma unroll
        for (int j = 0; j < 4; j++) {
            float2 m0 = m[j * 4], m1 = m[j * 4 + 1], m2 = m[j * 4 + 2], m3 = m[j * 4 + 3];
            float rr = m0.x * v0.x - m0.y * v0.y + m1.x * v1.x - m1.y * v1.y
                     + m2.x * v2.x - m2.y * v2.y + m3.x * v3.x - m3.y * v3.y;
            float ri = m0.x * v0.y + m0.y * v0.x + m1.x * v1.y + m1.y * v1.x
                     + m2.x * v2.y + m2.y * v2.x + m3.x * v3.y + m3.y * v3.x;
            s[i0 | (j << pl)] = make_float2(rr, ri);
        }
    }
}

// ---------------- Pass H: bonds 0..8 on combined bits 11..2 ----------------
__global__ void pass_high(const float* __restrict__ x) {
    __shared__ float2 s[1024 * LOWC];
    const int b    = blockIdx.y;
    const int low0 = blockIdx.x * LOWC;
    const int tid  = threadIdx.x;
    const float* xb = x + (size_t)b * DIM;

    for (int e = tid; e < 1024 * LOWC; e += blockDim.x) {
        int l = e & (LOWC - 1), h = e >> 2;
        s[e] = make_float2(xb[h * 1024 + low0 + l], 0.f);
    }
    __syncthreads();
    for (int q = 0; q < 9; q++) {
        apply2q(s, 1024, (8 - q) + 2, g_fused[q], tid, blockDim.x);
        __syncthreads();
    }
    float2* pb = g_psi + (size_t)b * DIM;
    for (int e = tid; e < 1024 * LOWC; e += blockDim.x) {
        int l = e & (LOWC - 1), h = e >> 2;
        pb[h * 1024 + low0 + l] = s[e];
    }
}

// ---------------- fp16 pack helper ----------------
__device__ __forceinline__ uint32_t pk2(float a, float b) {
    __half ha = __float2half_rn(a), hb = __float2half_rn(b);
    return (uint32_t)__half_as_ushort(ha) | ((uint32_t)__half_as_ushort(hb) << 16);
}

// ---------------- Pass L: bonds 9..18 on bits 10..0; emit 6 packed planes ----------------
__global__ void pass_low() {
    __shared__ float2 s[2048];
    const int b = blockIdx.y;
    const size_t base = (size_t)b * DIM + (size_t)blockIdx.x * 2048;
    const int tid = threadIdx.x;

    for (int e = tid; e < 2048; e += blockDim.x) s[e] = g_psi[base + e];
    __syncthreads();
    for (int q = 9; q < 19; q++) {
        apply2q(s, 512, 18 - q, g_fused[q], tid, blockDim.x);
        __syncthreads();
    }

    // tile = k-pair (2*blockIdx.x, 2*blockIdx.x+1) x all 1024 cols
    const size_t ci0 = ((size_t)b << 19) + ((size_t)blockIdx.x << 10);
    for (int c = tid; c < 1024; c += blockDim.x) {
        float2 v0 = s[c];            // k even
        float2 v1 = s[c + 1024];     // k odd
        float r0 = v0.x, i0 = v0.y, r1 = v1.x, i1 = v1.y;
        float d0 = i0 - r0, d1 = i1 - r1;
        float s0 = r0 + i0, s1 = r1 + i1;
        __half rh0 = __float2half_rn(r0), rh1 = __float2half_rn(r1);
        __half ih0 = __float2half_rn(i0), ih1 = __float2half_rn(i1);
        size_t ci = ci0 + c;
        g_tp32[0 * PSTR + ci] = (uint32_t)__half_as_ushort(rh0) | ((uint32_t)__half_as_ushort(rh1) << 16);
        g_tp32[1 * PSTR + ci] = pk2(r0 - __half2float(rh0), r1 - __half2float(rh1));
        g_tp32[2 * PSTR + ci] = (uint32_t)__half_as_ushort(ih0) | ((uint32_t)__half_as_ushort(ih1) << 16);
        g_tp32[3 * PSTR + ci] = pk2(i0 - __half2float(ih0), i1 - __half2float(ih1));
        g_tp32[4 * PSTR + ci] = pk2(d0, d1);
        g_tp32[5 * PSTR + ci] = pk2(s0, s1);
    }
}

// ---------------- rdm GEMM v8: k32 stages, 5 A planes (dL dropped), fp16 Gauss ----------------
// Block tile 64(a) x 128(c); warp 32x32; t1=Ar*Br, t2=Ai*Bi, t3=(Ai-Ar)*(Br+Bi).
// t1,t2 keep the 2-term A split; t3 uses hi only (error ~2^-11 of that product).
#define AS 72            // A smem col stride (uint32), ≡8 mod 32 -> conflict-free
#define BS 136           // B stride
#define A_PL_B (16 * AS * 4)           // 4608 B per A plane (16 kpairs = k32)
#define B_PL_B (16 * BS * 4)           // 8704 B per B plane
#define A_ALL_B (5 * A_PL_B)           // 23040
#define STG_B  (A_ALL_B + 3 * B_PL_B)  // 49152
#define NSTG   2
#define GEMM_SMEM (NSTG * STG_B)       // 98304

__device__ __forceinline__ void mma_f16(float* d, uint32_t a0, uint32_t a1,
                                        uint32_t a2, uint32_t a3,
                                        uint32_t b0, uint32_t b1) {
    asm volatile(
        "mma.sync.aligned.m16n8k16.row.col.f32.f16.f16.f32 "
        "{%0,%1,%2,%3},{%4,%5,%6,%7},{%8,%9},{%0,%1,%2,%3};"
        : "+f"(d[0]), "+f"(d[1]), "+f"(d[2]), "+f"(d[3])
        : "r"(a0), "r"(a1), "r"(a2), "r"(a3), "r"(b0), "r"(b1));
}
__device__ __forceinline__ void cp_async16(void* smem_ptr, const void* gptr) {
    uint32_t sa = (uint32_t)__cvta_generic_to_shared(smem_ptr);
    asm volatile("cp.async.cg.shared.global [%0], [%1], 16;" :: "r"(sa), "l"(gptr));
}
__device__ __forceinline__ void cp_commit() { asm volatile("cp.async.commit_group;"); }
__device__ __forceinline__ void cp_wait1()  { asm volatile("cp.async.wait_group 1;"); }

__global__ void __launch_bounds__(256, 2) rdm_gemm(float* __restrict__ out) {
    extern __shared__ char smem[];

    // decode linear block -> (col tile tcc of 128, row tile ta of 64), ta <= 2*tcc+1
    int tcc = 0, rem = blockIdx.x;
    while (rem >= 2 * tcc + 2) { rem -= 2 * tcc + 2; tcc++; }
    int ta = rem;

    const int b = blockIdx.y;
    const int a0b = ta * 64, c0b = tcc * 128;
    const int tid  = threadIdx.x;
    const int wid  = tid >> 5;
    const int lane = tid & 31;
    const int g    = lane >> 2;
    const int t4   = lane & 3;
    const int warpM = wid & 1;     // a offset 0/32
    const int warpN = wid >> 1;    // c offset 0/32/64/96

    float acc[3][2][4][4] = {};    // [product][mi][ni][reg]

    // one stage = k32 = 16 kpairs: A 5 planes x 16 kp x 16 chunks = 1280;
    // B 3 planes x 16 kp x 32 chunks = 1536; total 2816 = 11 * 256.
    auto stage = [&](int st) {
        char* sb = smem + (st & 1) * STG_B;
        const int kr0 = st * 16;
#pragma unroll
        for (int j = 0; j < 11; j++) {
            int cid = tid + j * 256;
            if (cid < 1280) {                       // A planes 0..4
                int pl = cid >> 8;
                int rm = cid & 255;
                int kp = rm >> 4, ch = rm & 15;
                const uint32_t* src = g_tp32 + (size_t)pl * PSTR + ((size_t)b << 19)
                                    + ((size_t)(kr0 + kp) << 10) + a0b + ch * 4;
                cp_async16(sb + pl * A_PL_B + kp * (AS * 4) + ch * 16, src);
            } else {                                // B: planes {rH=0,iH=2,sH=5}
                int d2 = cid - 1280;
                int p = d2 >> 9;
                int rm = d2 & 511;
                int kp = rm >> 5, ch = rm & 31;
                int gp = (p == 0) ? 0 : ((p == 1) ? 2 : 5);
                const uint32_t* src = g_tp32 + (size_t)gp * PSTR + ((size_t)b << 19)
                                    + ((size_t)(kr0 + kp) << 10) + c0b + ch * 4;
                cp_async16(sb + A_ALL_B + p * B_PL_B + kp * (BS * 4) + ch * 16, src);
            }
        }
        cp_commit();
    };

    stage(0);
    stage(1);

    for (int st = 0; st < 32; st++) {
        cp_wait1();
        __syncthreads();
        const char* sb = smem + (st & 1) * STG_B;

#pragma unroll
        for (int half = 0; half < 2; half++) {      // two k16 sub-chunks
            const int kofs = half * 8;              // kpair offset
#pragma unroll
            for (int p = 0; p < 3; p++) {
                const int plH = (p == 2) ? 4 : 2 * p;
                const uint32_t* paH = (const uint32_t*)(sb + plH * A_PL_B) + kofs * AS;
                const uint32_t* pB  = (const uint32_t*)(sb + A_ALL_B + p * B_PL_B) + kofs * BS;

                uint32_t Ah[2][4];
#pragma unroll
                for (int mi = 0; mi < 2; mi++) {
                    int col = warpM * 32 + mi * 16 + g;
                    Ah[mi][0] = paH[t4 * AS + col];
                    Ah[mi][1] = paH[t4 * AS + col + 8];
                    Ah[mi][2] = paH[(t4 + 4) * AS + col];
                    Ah[mi][3] = paH[(t4 + 4) * AS + col + 8];
                }
                uint32_t Bf[4][2];
#pragma unroll
                for (int ni = 0; ni < 4; ni++) {
                    int col = warpN * 32 + ni * 8 + g;
                    Bf[ni][0] = pB[t4 * BS + col];
                    Bf[ni][1] = pB[(t4 + 4) * BS + col];
                }
#pragma unroll
                for (int ni = 0; ni < 4; ni++)
#pragma unroll
                    for (int mi = 0; mi < 2; mi++)
                        mma_f16(acc[p][mi][ni], Ah[mi][0], Ah[mi][1], Ah[mi][2], Ah[mi][3],
                                Bf[ni][0], Bf[ni][1]);

                if (p < 2) {                        // lo sweep only for t1, t2
                    const uint32_t* paL = (const uint32_t*)(sb + (2 * p + 1) * A_PL_B) + kofs * AS;
                    uint32_t Al[2][4];
#pragma unroll
                    for (int mi = 0; mi < 2; mi++) {
                        int col = warpM * 32 + mi * 16 + g;
                        Al[mi][0] = paL[t4 * AS + col];
                        Al[mi][1] = paL[t4 * AS + col + 8];
                        Al[mi][2] = paL[(t4 + 4) * AS + col];
                        Al[mi][3] = paL[(t4 + 4) * AS + col + 8];
                    }
#pragma unroll
                    for (int ni = 0; ni < 4; ni++)
#pragma unroll
                        for (int mi = 0; mi < 2; mi++)
                            mma_f16(acc[p][mi][ni], Al[mi][0], Al[mi][1], Al[mi][2], Al[mi][3],
                                    Bf[ni][0], Bf[ni][1]);
                }
            }
        }
        __syncthreads();

        if (st + 2 < 32) stage(st + 2);
        else             cp_commit();
    }

    // ---- epilogue: R = t1+t2, I = t3+t1-t2; exactly-once Hermitian writes ----
    float2* out2 = (float2*)out;
#pragma unroll
    for (int mi = 0; mi < 2; mi++)
#pragma unroll
        for (int ni = 0; ni < 4; ni++)
#pragma unroll
            for (int r = 0; r < 4; r++) {
                int a = a0b + warpM * 32 + mi * 16 + g + ((r & 2) ? 8 : 0);
                int c = c0b + warpN * 32 + ni * 8 + 2 * t4 + (r & 1);
                float t1 = acc[0][mi][ni][r];
                float t2 = acc[1][mi][ni][r];
                float t3 = acc[2][mi][ni][r];
                float vr = t1 + t2;
                float vi = t3 + t1 - t2;
                if (a <= c)
                    out2[(size_t)(b * 1024 + a) * 1024 + c] = make_float2(vr, vi);
                if (a < c)
                    out2[(size_t)(b * 1024 + c) * 1024 + a] = make_float2(vr, -vi);
            }
}

// ---------------- launch ----------------
extern "C" void kernel_launch(void* const* d_in, const int* in_sizes, int n_in,
                              void* d_out, int out_size) {
    const float* x = (const float*)d_in[0];
    const float* w = (const float*)d_in[1];
    float* out = (float*)d_out;

    cudaFuncSetAttribute(rdm_gemm, cudaFuncAttributeMaxDynamicSharedMemorySize, GEMM_SMEM);

    precompute_gates<<<1, 32>>>(w);
    pass_high<<<dim3(1024 / LOWC, BATCH), 256>>>(x);
    pass_low<<<dim3(512, BATCH), 256>>>();
    rdm_gemm<<<dim3(72, BATCH), 256, GEMM_SMEM>>>(out);
}

// round 12
// speedup vs baseline: 1.3068x; 1.0669x over previous
#include <cuda_runtime.h>
#include <cuda_fp16.h>
#include <math.h>
#include <stdint.h>

#define NQ    20
#define DIM   (1u << NQ)
#define BATCH 4
#define LOWC  4

// ---------------- global scratch ----------------
static __device__ float2 g_psi[(size_t)BATCH * DIM];   // state after pass_high
// 5 packed-fp16 planes [plane][b][kpair][col], uint32 = {k even (lo), k odd (hi)}
// planes: 0=rH 1=rL 2=iH 3=dH 4=sH   (d = i - r, s = r + i)
static __device__ uint32_t g_tp32[(size_t)5 * BATCH * (DIM / 2)];
static __device__ float2 g_fused[NQ - 1][16];          // fused 4x4 gates
#define PSTR ((size_t)BATCH << 19)                     // uint32s per plane

// ---------------- complex helpers ----------------
__device__ __forceinline__ float2 cmul(float2 a, float2 b) {
    return make_float2(a.x * b.x - a.y * b.y, a.x * b.y + a.y * b.x);
}
__device__ __forceinline__ float2 cadd(float2 a, float2 b) {
    return make_float2(a.x + b.x, a.y + b.y);
}
__device__ void mat2mul(const float2* A, const float2* B, float2* C) {
    for (int i = 0; i < 2; i++)
        for (int j = 0; j < 2; j++) {
            float2 s = make_float2(0.f, 0.f);
            for (int k = 0; k < 2; k++) s = cadd(s, cmul(A[i * 2 + k], B[k * 2 + j]));
            C[i * 2 + j] = s;
        }
}
__device__ void mat4mul(const float2* A, const float2* B, float2* C) {
    for (int i = 0; i < 4; i++)
        for (int j = 0; j < 4; j++) {
            float2 s = make_float2(0.f, 0.f);
            for (int k = 0; k < 4; k++) s = cadd(s, cmul(A[i * 4 + k], B[k * 4 + j]));
            C[i * 4 + j] = s;
        }
}
__device__ void kron22(const float2* A, const float2* B, float2* C) {
    for (int i2 = 0; i2 < 2; i2++)
        for (int i1 = 0; i1 < 2; i1++)
            for (int j2 = 0; j2 < 2; j2++)
                for (int j1 = 0; j1 < 2; j1++)
                    C[(i2 * 2 + i1) * 4 + (j2 * 2 + j1)] = cmul(A[i2 * 2 + j2], B[i1 * 2 + j1]);
}

// ---------------- gate precompute ----------------
__global__ void precompute_gates(const float* __restrict__ w) {
    const float WM = 0.6324555320336759f;  // sqrt(2/5)
    __shared__ float2 U1[NQ][4];
    __shared__ float2 U2[NQ][4];
    int t = threadIdx.x;
    if (t < NQ) {
        for (int layer = 0; layer < 2; layer++) {
            int base = (layer == 0) ? 0 : (6 * NQ - 3);
            float tx = w[base + 3 * t]     * WM;
            float ty = w[base + 3 * t + 1] * WM;
            float tz = w[base + 3 * t + 2] * WM;
            float cx = cosf(0.5f * tx), sx = sinf(0.5f * tx);
            float cy = cosf(0.5f * ty), sy = sinf(0.5f * ty);
            float cz = cosf(0.5f * tz), sz = sinf(0.5f * tz);
            float2 Rx[4] = { {cx,0.f}, {0.f,-sx}, {0.f,-sx}, {cx,0.f} };
            float2 Ry[4] = { {cy,0.f}, {-sy,0.f}, {sy,0.f},  {cy,0.f} };
            float2 Rz[4] = { {cz,-sz}, {0.f,0.f}, {0.f,0.f}, {cz,sz} };
            float2 T[4], U[4];
            mat2mul(Ry, Rx, T);
            mat2mul(Rz, T, U);
            float2* dst = (layer == 0) ? U1[t] : U2[t];
            for (int i = 0; i < 4; i++) dst[i] = U[i];
        }
    }
    __syncthreads();
    if (t < NQ - 1) {
        float a = w[3 * NQ + 3 * t]     * WM;
        float b = w[3 * NQ + 3 * t + 1] * WM;
        float c = w[3 * NQ + 3 * t + 2] * WM;
        float ca = cosf(0.5f * a), sa = sinf(0.5f * a);
        float cb = cosf(0.5f * b), sb = sinf(0.5f * b);
        float cc = cosf(0.5f * c), sc = sinf(0.5f * c);
        float2 Rxx[16], Ryy[16], Rzz[16];
        for (int i = 0; i < 16; i++) {
            Rxx[i] = make_float2(0.f, 0.f);
            Ryy[i] = make_float2(0.f, 0.f);
            Rzz[i] = make_float2(0.f, 0.f);
        }
        for (int i = 0; i < 4; i++) {
            Rxx[i * 4 + i] = make_float2(ca, 0.f);
            Ryy[i * 4 + i] = make_float2(cb, 0.f);
        }
        Rxx[3]  = make_float2(0.f, -sa);
        Rxx[6]  = make_float2(0.f, -sa);
        Rxx[9]  = make_float2(0.f, -sa);
        Rxx[12] = make_float2(0.f, -sa);
        Ryy[3]  = make_float2(0.f,  sb);
        Ryy[6]  = make_float2(0.f, -sb);
        Ryy[9]  = make_float2(0.f, -sb);
        Ryy[12] = make_float2(0.f,  sb);
        Rzz[0]  = make_float2(cc, -sc);
        Rzz[5]  = make_float2(cc,  sc);
        Rzz[10] = make_float2(cc,  sc);
        Rzz[15] = make_float2(cc, -sc);
        float2 T[16], Bq[16];
        mat4mul(Ryy, Rxx, T);
        mat4mul(Rzz, T, Bq);

        float2 I2m[4] = { {1.f,0.f},{0.f,0.f},{0.f,0.f},{1.f,0.f} };
        float2 R[16], G[16];
        if (t == 0) kron22(U1[0], U1[1], R);
        else        kron22(I2m, U1[t + 1], R);
        mat4mul(Bq, R, G);
        if (t >= 10) {
            float2 L[16], G2[16];
            if (t == 18) kron22(U2[18], U2[19], L);
            else         kron22(U2[t], I2m, L);
            mat4mul(L, G, G2);
            for (int i = 0; i < 16; i++) G[i] = G2[i];
        }
        for (int i = 0; i < 16; i++) g_fused[t][i] = G[i];
    }
}

// ---------------- 2q gate on shared tile (lean, proven) ----------------
__device__ __forceinline__ void apply2q(float2* s, int nquads, int pl,
                                        const float2* __restrict__ Mg,
                                        int tid, int nth) {
    float2 m[16];
#pragma unroll
    for (int i = 0; i < 16; i++) m[i] = Mg[i];
    for (int p = tid; p < nquads; p += nth) {
        int lowm = p & ((1 << pl) - 1);
        int i0 = ((p >> pl) << (pl + 2)) | lowm;
        float2 v0 = s[i0];
        float2 v1 = s[i0 | (1 << pl)];
        float2 v2 = s[i0 | (2 << pl)];
        float2 v3 = s[i0 | (3 << pl)];
#pragma unroll
        for (int j = 0; j < 4; j++) {
            float2 m0 = m[j * 4], m1 = m[j * 4 + 1], m2 = m[j * 4 + 2], m3 = m[j * 4 + 3];
            float rr = m0.x * v0.x - m0.y * v0.y + m1.x * v1.x - m1.y * v1.y
                     + m2.x * v2.x - m2.y * v2.y + m3.x * v3.x - m3.y * v3.y;
            float ri = m0.x * v0.y + m0.y * v0.x + m1.x * v1.y + m1.y * v1.x
                     + m2.x * v2.y + m2.y * v2.x + m3.x * v3.y + m3.y * v3.x;
            s[i0 | (j << pl)] = make_float2(rr, ri);
        }
    }
}

// ---------------- Pass H: bonds 0..8 on combined bits 11..2 ----------------
__global__ void pass_high(const float* __restrict__ x) {
    __shared__ float2 s[1024 * LOWC];
    const int b    = blockIdx.y;
    const int low0 = blockIdx.x * LOWC;
    const int tid  = threadIdx.x;
    const float* xb = x + (size_t)b * DIM;

    for (int e = tid; e < 1024 * LOWC; e += blockDim.x) {
        int l = e & (LOWC - 1), h = e >> 2;
        s[e] = make_float2(xb[h * 1024 + low0 + l], 0.f);
    }
    __syncthreads();
    for (int q = 0; q < 9; q++) {
        apply2q(s, 1024, (8 - q) + 2, g_fused[q], tid, blockDim.x);
        __syncthreads();
    }
    float2* pb = g_psi + (size_t)b * DIM;
    for (int e = tid; e < 1024 * LOWC; e += blockDim.x) {
        int l = e & (LOWC - 1), h = e >> 2;
        pb[h * 1024 + low0 + l] = s[e];
    }
}

// ---------------- fp16 pack helper ----------------
__device__ __forceinline__ uint32_t pk2(float a, float b) {
    __half ha = __float2half_rn(a), hb = __float2half_rn(b);
    return (uint32_t)__half_as_ushort(ha) | ((uint32_t)__half_as_ushort(hb) << 16);
}

// ---------------- Pass L: bonds 9..18 on bits 10..0; emit 5 packed planes ----------------
__global__ void pass_low() {
    __shared__ float2 s[2048];
    const int b = blockIdx.y;
    const size_t base = (size_t)b * DIM + (size_t)blockIdx.x * 2048;
    const int tid = threadIdx.x;

    for (int e = tid; e < 2048; e += blockDim.x) s[e] = g_psi[base + e];
    __syncthreads();
    for (int q = 9; q < 19; q++) {
        apply2q(s, 512, 18 - q, g_fused[q], tid, blockDim.x);
        __syncthreads();
    }

    // tile = k-pair (2*blockIdx.x, 2*blockIdx.x+1) x all 1024 cols
    const size_t ci0 = ((size_t)b << 19) + ((size_t)blockIdx.x << 10);
    for (int c = tid; c < 1024; c += blockDim.x) {
        float2 v0 = s[c];            // k even
        float2 v1 = s[c + 1024];     // k odd
        float r0 = v0.x, i0 = v0.y, r1 = v1.x, i1 = v1.y;
        float d0 = i0 - r0, d1 = i1 - r1;
        float s0 = r0 + i0, s1 = r1 + i1;
        __half rh0 = __float2half_rn(r0), rh1 = __float2half_rn(r1);
        size_t ci = ci0 + c;
        g_tp32[0 * PSTR + ci] = (uint32_t)__half_as_ushort(rh0) | ((uint32_t)__half_as_ushort(rh1) << 16);
        g_tp32[1 * PSTR + ci] = pk2(r0 - __half2float(rh0), r1 - __half2float(rh1));
        g_tp32[2 * PSTR + ci] = pk2(i0, i1);
        g_tp32[3 * PSTR + ci] = pk2(d0, d1);
        g_tp32[4 * PSTR + ci] = pk2(s0, s1);
    }
}

// ---------------- rdm GEMM v9: k32 stages, 4 A planes, 32 MMAs/k16, fp16 Gauss ----------
// Block tile 64(a) x 128(c); warp 32x32; t1=Ar*Br, t2=Ai*Bi, t3=(Ai-Ar)*(Br+Bi).
// t1 keeps the 2-term A split; t2, t3 hi-only (per-term error ~2^-11, averages over K).
#define AS 72            // A smem col stride (uint32), ≡8 mod 32 -> conflict-free
#define BS 136           // B stride
#define A_PL_B (16 * AS * 4)           // 4608 B per A plane (16 kpairs = k32)
#define B_PL_B (16 * BS * 4)           // 8704 B per B plane
#define A_ALL_B (4 * A_PL_B)           // 18432
#define STG_B  (A_ALL_B + 3 * B_PL_B)  // 44544
#define NSTG   2
#define GEMM_SMEM (NSTG * STG_B)       // 89088

__device__ __forceinline__ void mma_f16(float* d, uint32_t a0, uint32_t a1,
                                        uint32_t a2, uint32_t a3,
                                        uint32_t b0, uint32_t b1) {
    asm volatile(
        "mma.sync.aligned.m16n8k16.row.col.f32.f16.f16.f32 "
        "{%0,%1,%2,%3},{%4,%5,%6,%7},{%8,%9},{%0,%1,%2,%3};"
        : "+f"(d[0]), "+f"(d[1]), "+f"(d[2]), "+f"(d[3])
        : "r"(a0), "r"(a1), "r"(a2), "r"(a3), "r"(b0), "r"(b1));
}
__device__ __forceinline__ void cp_async16(void* smem_ptr, const void* gptr) {
    uint32_t sa = (uint32_t)__cvta_generic_to_shared(smem_ptr);
    asm volatile("cp.async.cg.shared.global [%0], [%1], 16;" :: "r"(sa), "l"(gptr));
}
__device__ __forceinline__ void cp_commit() { asm volatile("cp.async.commit_group;"); }
__device__ __forceinline__ void cp_wait1()  { asm volatile("cp.async.wait_group 1;"); }

__global__ void __launch_bounds__(256, 2) rdm_gemm(float* __restrict__ out) {
    extern __shared__ char smem[];

    // decode linear block -> (col tile tcc of 128, row tile ta of 64), ta <= 2*tcc+1
    int tcc = 0, rem = blockIdx.x;
    while (rem >= 2 * tcc + 2) { rem -= 2 * tcc + 2; tcc++; }
    int ta = rem;

    const int b = blockIdx.y;
    const int a0b = ta * 64, c0b = tcc * 128;
    const int tid  = threadIdx.x;
    const int wid  = tid >> 5;
    const int lane = tid & 31;
    const int g    = lane >> 2;
    const int t4   = lane & 3;
    const int warpM = wid & 1;     // a offset 0/32
    const int warpN = wid >> 1;    // c offset 0/32/64/96

    float acc[3][2][4][4] = {};    // [product][mi][ni][reg]

    // one stage = k32 = 16 kpairs: A 4 planes x 16 kp x 16 chunks = 1024;
    // B 3 planes x 16 kp x 32 chunks = 1536; total 2560 = 10 * 256.
    auto stage = [&](int st) {
        char* sb = smem + (st & 1) * STG_B;
        const int kr0 = st * 16;
#pragma unroll
        for (int j = 0; j < 10; j++) {
            int cid = tid + j * 256;
            if (cid < 1024) {                       // A planes 0..3 (rH,rL,iH,dH)
                int pl = cid >> 8;
                int rm = cid & 255;
                int kp = rm >> 4, ch = rm & 15;
                const uint32_t* src = g_tp32 + (size_t)pl * PSTR + ((size_t)b << 19)
                                    + ((size_t)(kr0 + kp) << 10) + a0b + ch * 4;
                cp_async16(sb + pl * A_PL_B + kp * (AS * 4) + ch * 16, src);
            } else {                                // B: planes {rH=0,iH=2,sH=4}
                int d2 = cid - 1024;
                int p = d2 >> 9;
                int rm = d2 & 511;
                int kp = rm >> 5, ch = rm & 31;
                int gp = (p == 0) ? 0 : ((p == 1) ? 2 : 4);
                const uint32_t* src = g_tp32 + (size_t)gp * PSTR + ((size_t)b << 19)
                                    + ((size_t)(kr0 + kp) << 10) + c0b + ch * 4;
                cp_async16(sb + A_ALL_B + p * B_PL_B + kp * (BS * 4) + ch * 16, src);
            }
        }
        cp_commit();
    };

    stage(0);
    stage(1);

    for (int st = 0; st < 32; st++) {
        cp_wait1();
        __syncthreads();
        const char* sb = smem + (st & 1) * STG_B;

#pragma unroll
        for (int half = 0; half < 2; half++) {      // two k16 sub-chunks
            const int kofs = half * 8;              // kpair offset
#pragma unroll
            for (int p = 0; p < 3; p++) {
                const int plH = (p == 0) ? 0 : ((p == 1) ? 2 : 3);   // rH / iH / dH
                const uint32_t* paH = (const uint32_t*)(sb + plH * A_PL_B) + kofs * AS;
                const uint32_t* pB  = (const uint32_t*)(sb + A_ALL_B + p * B_PL_B) + kofs * BS;

                uint32_t Ah[2][4];
#pragma unroll
                for (int mi = 0; mi < 2; mi++) {
                    int col = warpM * 32 + mi * 16 + g;
                    Ah[mi][0] = paH[t4 * AS + col];
                    Ah[mi][1] = paH[t4 * AS + col + 8];
                    Ah[mi][2] = paH[(t4 + 4) * AS + col];
                    Ah[mi][3] = paH[(t4 + 4) * AS + col + 8];
                }
                uint32_t Bf[4][2];
#pragma unroll
                for (int ni = 0; ni < 4; ni++) {
                    int col = warpN * 32 + ni * 8 + g;
                    Bf[ni][0] = pB[t4 * BS + col];
                    Bf[ni][1] = pB[(t4 + 4) * BS + col];
                }
#pragma unroll
                for (int ni = 0; ni < 4; ni++)
#pragma unroll
                    for (int mi = 0; mi < 2; mi++)
                        mma_f16(acc[p][mi][ni], Ah[mi][0], Ah[mi][1], Ah[mi][2], Ah[mi][3],
                                Bf[ni][0], Bf[ni][1]);

                if (p == 0) {                       // lo sweep only for t1 (rL)
                    const uint32_t* paL = (const uint32_t*)(sb + 1 * A_PL_B) + kofs * AS;
                    uint32_t Al[2][4];
#pragma unroll
                    for (int mi = 0; mi < 2; mi++) {
                        int col = warpM * 32 + mi * 16 + g;
                        Al[mi][0] = paL[t4 * AS + col];
                        Al[mi][1] = paL[t4 * AS + col + 8];
                        Al[mi][2] = paL[(t4 + 4) * AS + col];
                        Al[mi][3] = paL[(t4 + 4) * AS + col + 8];
                    }
#pragma unroll
                    for (int ni = 0; ni < 4; ni++)
#pragma unroll
                        for (int mi = 0; mi < 2; mi++)
                            mma_f16(acc[p][mi][ni], Al[mi][0], Al[mi][1], Al[mi][2], Al[mi][3],
                                    Bf[ni][0], Bf[ni][1]);
                }
            }
        }
        __syncthreads();

        if (st + 2 < 32) stage(st + 2);
        else             cp_commit();
    }

    // ---- epilogue: R = t1+t2, I = t3+t1-t2; exactly-once Hermitian writes ----
    float2* out2 = (float2*)out;
#pragma unroll
    for (int mi = 0; mi < 2; mi++)
#pragma unroll
        for (int ni = 0; ni < 4; ni++)
#pragma unroll
            for (int r = 0; r < 4; r++) {
                int a = a0b + warpM * 32 + mi * 16 + g + ((r & 2) ? 8 : 0);
                int c = c0b + warpN * 32 + ni * 8 + 2 * t4 + (r & 1);
                float t1 = acc[0][mi][ni][r];
                float t2 = acc[1][mi][ni][r];
                float t3 = acc[2][mi][ni][r];
                float vr = t1 + t2;
                float vi = t3 + t1 - t2;
                if (a <= c)
                    out2[(size_t)(b * 1024 + a) * 1024 + c] = make_float2(vr, vi);
                if (a < c)
                    out2[(size_t)(b * 1024 + c) * 1024 + a] = make_float2(vr, -vi);
            }
}

// ---------------- launch ----------------
extern "C" void kernel_launch(void* const* d_in, const int* in_sizes, int n_in,
                              void* d_out, int out_size) {
    const float* x = (const float*)d_in[0];
    const float* w = (const float*)d_in[1];
    float* out = (float*)d_out;

    cudaFuncSetAttribute(rdm_gemm, cudaFuncAttributeMaxDynamicSharedMemorySize, GEMM_SMEM);

    precompute_gates<<<1, 32>>>(w);
    pass_high<<<dim3(1024 / LOWC, BATCH), 256>>>(x);
    pass_low<<<dim3(512, BATCH), 256>>>();
    rdm_gemm<<<dim3(72, BATCH), 256, GEMM_SMEM>>>(out);
}